// round 10
// baseline (speedup 1.0000x reference)
#include <cuda_runtime.h>
#include <cstdint>

#define NN   10000
#define EE   320000
#define GG   64
#define NIN  64
#define EIN  16
#define HID  256

// ---------------- scratch (device-side only; NEVER passed from host) ----------------
__device__ __align__(16) float g_W0c[HID * NIN];    // tf32(we2 @ l0_lw)
__device__ __align__(16) float g_c0[NIN];           // be2 @ l0_lw + l0_lb
__device__ __align__(16) float g_W1c[HID * HID];    // tf32(we2 @ l1_lw)
__device__ __align__(16) float g_c1[HID];           // be2 @ l1_lw + l1_lb
__device__ __align__(16) float g_agg0[NN * NIN];
__device__ __align__(16) float g_agg1[NN * HID];
__device__ __align__(16) float g_t0[NN * HID];
__device__ __align__(16) float g_x1[NN * HID];
__device__ __align__(16) float g_x2[NN * HID];
__device__ __align__(16) float g_psum[GG * HID];
__device__ float g_pcnt[GG];
__device__ int   g_is64;

// ---------------- helpers ----------------
__device__ __forceinline__ int load_idx(const void* p, long long i) {
    if (g_is64) return (int)((const long long*)p)[i];
    return ((const int*)p)[i];
}

__device__ __forceinline__ void red_add_v4(float* p, float a, float b, float c, float d) {
    asm volatile("red.global.add.v4.f32 [%0], {%1, %2, %3, %4};"
                 :: "l"(p), "f"(a), "f"(b), "f"(c), "f"(d) : "memory");
}

__device__ __forceinline__ float to_tf32(float x) {
    unsigned r;
    asm("cvt.rna.tf32.f32 %0, %1;" : "=r"(r) : "f"(x));
    return __uint_as_float(r);
}

// m16n8k8 tf32 MMA, D += A*B
__device__ __forceinline__ void mma_tf32(float* d,
    uint32_t a0, uint32_t a1, uint32_t a2, uint32_t a3,
    uint32_t b0, uint32_t b1)
{
    asm volatile(
        "mma.sync.aligned.m16n8k8.row.col.f32.tf32.tf32.f32 "
        "{%0,%1,%2,%3}, {%4,%5,%6,%7}, {%8,%9}, {%0,%1,%2,%3};"
        : "+f"(d[0]), "+f"(d[1]), "+f"(d[2]), "+f"(d[3])
        : "r"(a0), "r"(a1), "r"(a2), "r"(a3), "r"(b0), "r"(b1));
}

// zero scratch + detect index width (merged so edge_mma<0> is the 4th launch,
// which is the launch ncu captures)
__global__ void zero_kernel(const long long* eidx) {
    int i = blockIdx.x * 256 + threadIdx.x;   // grid covers NN*HID = 2.56M exactly
    if (i < NN * NIN) g_agg0[i] = 0.f;
    if (i < NN * HID) g_agg1[i] = 0.f;
    if (i < GG * HID) g_psum[i] = 0.f;
    if (i < GG)       g_pcnt[i] = 0.f;
    if (i == 0) {
        int is64 = 1;
        #pragma unroll 1
        for (int k = 0; k < 64; k++) {
            long long v = eidx[k];
            if (v < 0 || v >= NN) { is64 = 0; break; }
        }
        g_is64 = is64;
    }
}

// ---------------- weight folding: Wc = tf32(we2 @ lw) ; c = be2 @ lw + lb ----------------
// grid = 32 blocks; block 0 additionally computes the folded bias c.
template<int LAYER>
__global__ __launch_bounds__(256) void prep_wc(const float* __restrict__ we2,
                                               const float* __restrict__ lw,
                                               const float* __restrict__ be2,
                                               const float* __restrict__ lb) {
    constexpr int COUT = (LAYER == 0) ? NIN : HID;
    float* wc = (LAYER == 0) ? g_W0c : g_W1c;
    float* cv = (LAYER == 0) ? g_c0  : g_c1;
    __shared__ float lw_s[32][256];
    __shared__ float we2_s[8][33];
    const int i0 = blockIdx.x * 8;
    const int t = threadIdx.x;
    float acc[8];
    #pragma unroll
    for (int r = 0; r < 8; r++) acc[r] = 0.f;

    #pragma unroll 1
    for (int kc = 0; kc < HID; kc += 32) {
        __syncthreads();
        for (int i = t; i < 32 * COUT / 4; i += 256) {
            const int r = i / (COUT / 4), c = (i % (COUT / 4)) * 4;
            *(float4*)&lw_s[r][c] = __ldg((const float4*)&lw[(kc + r) * COUT + c]);
        }
        we2_s[t >> 5][t & 31] = we2[(i0 + (t >> 5)) * HID + kc + (t & 31)];
        __syncthreads();
        if (t < COUT) {
            #pragma unroll 4
            for (int k = 0; k < 32; k++) {
                const float wv = lw_s[k][t];
                #pragma unroll
                for (int r = 0; r < 8; r++) acc[r] = fmaf(we2_s[r][k], wv, acc[r]);
            }
        }
    }
    if (t < COUT) {
        #pragma unroll
        for (int r = 0; r < 8; r++) wc[(i0 + r) * COUT + t] = to_tf32(acc[r]);
        if (blockIdx.x == 0) {
            float a = lb[t];
            #pragma unroll 4
            for (int k = 0; k < HID; k++) a = fmaf(be2[k], lw[k * COUT + t], a);
            cv[t] = a;
        }
    }
}

// ---------------- fused edge kernel, TF32 mma.sync, 2 CTAs/SM ----------------
// 64 edges / block (M=64), 256 threads = 8 warps (4 across M, 2 across N).
// phase1: h1 = relu(ea@we1+be1) via MMA (K=16); phase2: ep = h1@Wc via MMA,
// K chunked by 32 through a single smem B tile; scatter via RED.128.
template<int LAYER>
__global__ __launch_bounds__(256, 2) void edge_mma(
    const float* __restrict__ ea,
    const long long* __restrict__ eidx,
    const float* __restrict__ we1,
    const float* __restrict__ be1,
    const float* __restrict__ x_arg)
{
    constexpr int COUT  = (LAYER == 0) ? NIN : HID;
    constexpr int NPAD1 = HID + 8;     // 264
    constexpr int NPAD2 = COUT + 8;
    constexpr int H1S   = HID + 4;     // 260
    constexpr int EAS   = 20;
    constexpr int BSZ   = (16 * NPAD1 > 32 * NPAD2) ? 16 * NPAD1 : 32 * NPAD2;

    const float* Wc   = (LAYER == 0) ? g_W0c : g_W1c;   // pre-rounded tf32
    const float* cvec = (LAYER == 0) ? g_c0  : g_c1;
    const float* xin  = (LAYER == 0) ? x_arg : g_x1;
    float*       agg  = (LAYER == 0) ? g_agg0 : g_agg1;

    extern __shared__ float sm[];
    float* ea_s  = sm;                    // 64*EAS
    float* h1_s  = ea_s + 64 * EAS;       // 64*H1S
    float* Bs    = h1_s + 64 * H1S;       // BSZ
    float* be1_s = Bs + BSZ;              // HID
    float* c_s   = be1_s + HID;           // COUT
    int*   src_s = (int*)(c_s + COUT);    // 64 ints
    int*   dst_s = src_s + 64;            // 64 ints

    const int t  = threadIdx.x;
    const long long e0 = (long long)blockIdx.x * 64;

    // ---- loads ----
    {   // ea: 64x16, one float4 per thread, tf32-rounded
        const int e = t >> 2, c = (t & 3) * 4;
        float4 v = *(const float4*)&ea[(e0 + e) * EIN + c];
        v.x = to_tf32(v.x); v.y = to_tf32(v.y); v.z = to_tf32(v.z); v.w = to_tf32(v.w);
        *(float4*)&ea_s[e * EAS + c] = v;
    }
    if (t < 64)       src_s[t]      = load_idx(eidx, e0 + t);
    else if (t < 128) dst_s[t - 64] = load_idx(eidx, (long long)EE + e0 + (t - 64));
    be1_s[t] = be1[t];
    if (t < COUT) c_s[t] = cvec[t];
    {   // we1 (16x256) into Bs, tf32-rounded
        const int r = t >> 4, cb = (t & 15) * 16;
        #pragma unroll
        for (int i = 0; i < 4; i++) {
            float4 v = __ldg((const float4*)&we1[r * HID + cb + i * 4]);
            v.x = to_tf32(v.x); v.y = to_tf32(v.y); v.z = to_tf32(v.z); v.w = to_tf32(v.w);
            *(float4*)&Bs[r * NPAD1 + cb + i * 4] = v;
        }
    }
    __syncthreads();

    const int w  = t >> 5, l = t & 31;
    const int lq = l >> 2, lr = l & 3;
    const int m_off = (w & 3) * 16;

    float d[16][4];

    // ---- phase 1: h1 = relu(ea @ we1 + be1), N=256 ----
    {
        const int nh1 = (w >> 2) * 128;
        #pragma unroll
        for (int nt = 0; nt < 16; nt++) { d[nt][0] = d[nt][1] = d[nt][2] = d[nt][3] = 0.f; }
        #pragma unroll
        for (int ks = 0; ks < 2; ks++) {
            const int k = ks * 8;
            const uint32_t a0 = __float_as_uint(ea_s[(m_off + lq) * EAS + k + lr]);
            const uint32_t a1 = __float_as_uint(ea_s[(m_off + lq + 8) * EAS + k + lr]);
            const uint32_t a2 = __float_as_uint(ea_s[(m_off + lq) * EAS + k + lr + 4]);
            const uint32_t a3 = __float_as_uint(ea_s[(m_off + lq + 8) * EAS + k + lr + 4]);
            #pragma unroll
            for (int nt = 0; nt < 16; nt++) {
                const int n = nh1 + nt * 8 + lq;
                const uint32_t b0 = __float_as_uint(Bs[(k + lr) * NPAD1 + n]);
                const uint32_t b1 = __float_as_uint(Bs[(k + lr + 4) * NPAD1 + n]);
                mma_tf32(d[nt], a0, a1, a2, a3, b0, b1);
            }
        }
        #pragma unroll
        for (int nt = 0; nt < 16; nt++) {
            const int n = nh1 + nt * 8 + lr * 2;
            const float bv0 = be1_s[n], bv1 = be1_s[n + 1];
            h1_s[(m_off + lq) * H1S + n]         = to_tf32(fmaxf(d[nt][0] + bv0, 0.f));
            h1_s[(m_off + lq) * H1S + n + 1]     = to_tf32(fmaxf(d[nt][1] + bv1, 0.f));
            h1_s[(m_off + lq + 8) * H1S + n]     = to_tf32(fmaxf(d[nt][2] + bv0, 0.f));
            h1_s[(m_off + lq + 8) * H1S + n + 1] = to_tf32(fmaxf(d[nt][3] + bv1, 0.f));
        }
    }

    // ---- phase 2: ep = h1 @ Wc, K=256 chunked by 32 ----
    constexpr int NT2 = (COUT == 256) ? 16 : 4;
    const int nh2 = (w >> 2) * (COUT / 2);
    #pragma unroll
    for (int nt = 0; nt < NT2; nt++) { d[nt][0] = d[nt][1] = d[nt][2] = d[nt][3] = 0.f; }

    #pragma unroll 1
    for (int kc = 0; kc < HID; kc += 32) {
        __syncthreads();   // prior Bs readers done
        for (int i = t; i < 32 * COUT / 4; i += 256) {
            const int r = i / (COUT / 4), c = (i % (COUT / 4)) * 4;
            *(float4*)&Bs[r * NPAD2 + c] = __ldg((const float4*)&Wc[(size_t)(kc + r) * COUT + c]);
        }
        __syncthreads();
        #pragma unroll
        for (int ks = 0; ks < 4; ks++) {
            const int k = ks * 8;
            const uint32_t a0 = __float_as_uint(h1_s[(m_off + lq) * H1S + kc + k + lr]);
            const uint32_t a1 = __float_as_uint(h1_s[(m_off + lq + 8) * H1S + kc + k + lr]);
            const uint32_t a2 = __float_as_uint(h1_s[(m_off + lq) * H1S + kc + k + lr + 4]);
            const uint32_t a3 = __float_as_uint(h1_s[(m_off + lq + 8) * H1S + kc + k + lr + 4]);
            #pragma unroll
            for (int nt = 0; nt < NT2; nt++) {
                const int n = nh2 + nt * 8 + lq;
                const uint32_t b0 = __float_as_uint(Bs[(k + lr) * NPAD2 + n]);
                const uint32_t b1 = __float_as_uint(Bs[(k + lr + 4) * NPAD2 + n]);
                mma_tf32(d[nt], a0, a1, a2, a3, b0, b1);
            }
        }
    }

    __syncthreads();   // all h1 reads done; safe to overwrite with ep
    #pragma unroll
    for (int nt = 0; nt < NT2; nt++) {
        const int n = nh2 + nt * 8 + lr * 2;
        h1_s[(m_off + lq) * H1S + n]         = d[nt][0];
        h1_s[(m_off + lq) * H1S + n + 1]     = d[nt][1];
        h1_s[(m_off + lq + 8) * H1S + n]     = d[nt][2];
        h1_s[(m_off + lq + 8) * H1S + n + 1] = d[nt][3];
    }
    __syncthreads();

    // ---- scatter: msg = relu(x[src] + ep + c) -> RED.128 into agg[dst] ----
    constexpr int CG = COUT / 4;
    for (int i = t; i < 64 * CG; i += 256) {
        const int e = i / CG, c = (i % CG) * 4;
        const float4 ep = *(const float4*)&h1_s[e * H1S + c];
        const float4 xv = __ldg((const float4*)&xin[(size_t)src_s[e] * COUT + c]);
        const float4 cv = *(const float4*)&c_s[c];
        red_add_v4(&agg[(size_t)dst_s[e] * COUT + c],
                   fmaxf(xv.x + ep.x + cv.x, 0.f),
                   fmaxf(xv.y + ep.y + cv.y, 0.f),
                   fmaxf(xv.z + ep.z + cv.z, 0.f),
                   fmaxf(xv.w + ep.w + cv.w, 0.f));
    }
}

template<int LAYER> struct EdgeSmem {
    static constexpr int COUT  = (LAYER == 0) ? NIN : HID;
    static constexpr int NPAD1 = HID + 8;
    static constexpr int NPAD2 = COUT + 8;
    static constexpr int BSZ   = (16 * NPAD1 > 32 * NPAD2) ? 16 * NPAD1 : 32 * NPAD2;
    static constexpr int FLOATS = 64 * 20 + 64 * (HID + 4) + BSZ + HID + COUT + 128;
    static constexpr int BYTES  = FLOATS * 4;
};

// ---------------- node MLP (fp32 FMA): C = relu((A [+ A2]) @ W + b) ----------------
// MODE 0: A=x (K=64) +g_agg0 -> g_t0 ; MODE 1: A=g_t0 -> g_x1
// MODE 2: A=g_x1 +g_agg1 -> g_t0     ; MODE 3: A=g_t0 -> g_x2
template<int MODE>
__global__ __launch_bounds__(256) void node_mlp(
    const float* __restrict__ x_arg,
    const float* __restrict__ W,
    const float* __restrict__ b)
{
    constexpr int  K   = (MODE == 0) ? NIN : HID;
    constexpr bool ADD = (MODE == 0) || (MODE == 2);
    const float* A  = (MODE == 0) ? x_arg :
                      (MODE == 2) ? g_x1  : g_t0;
    const float* A2 = (MODE == 0) ? g_agg0 : g_agg1;
    float*       C  = (MODE == 1) ? g_x1 :
                      (MODE == 3) ? g_x2 : g_t0;

    __shared__ float a_s[32][K + 4];
    const int t = threadIdx.x;
    const int r0 = blockIdx.x * 32;

    #pragma unroll 1
    for (int i = t; i < 32 * K; i += 256) {
        const int r = i / K, k = i % K;
        float v = 0.f;
        if (r0 + r < NN) {
            v = A[(size_t)(r0 + r) * K + k];
            if (ADD) v += A2[(size_t)(r0 + r) * K + k];
        }
        a_s[r][k] = v;
    }
    __syncthreads();

    const int j0 = (t % 64) * 4;
    const int rb = (t / 64) * 8;
    float acc[8][4];
    #pragma unroll
    for (int r = 0; r < 8; r++) { acc[r][0] = acc[r][1] = acc[r][2] = acc[r][3] = 0.f; }

    #pragma unroll 1
    for (int k = 0; k < K; k += 4) {
        const float4 w0 = __ldg((const float4*)&W[(k + 0) * HID + j0]);
        const float4 w1 = __ldg((const float4*)&W[(k + 1) * HID + j0]);
        const float4 w2 = __ldg((const float4*)&W[(k + 2) * HID + j0]);
        const float4 w3 = __ldg((const float4*)&W[(k + 3) * HID + j0]);
        #pragma unroll
        for (int r = 0; r < 8; r++) {
            const float4 a = *(const float4*)&a_s[rb + r][k];
            acc[r][0] = fmaf(a.x, w0.x, acc[r][0]);
            acc[r][1] = fmaf(a.x, w0.y, acc[r][1]);
            acc[r][2] = fmaf(a.x, w0.z, acc[r][2]);
            acc[r][3] = fmaf(a.x, w0.w, acc[r][3]);
            acc[r][0] = fmaf(a.y, w1.x, acc[r][0]);
            acc[r][1] = fmaf(a.y, w1.y, acc[r][1]);
            acc[r][2] = fmaf(a.y, w1.z, acc[r][2]);
            acc[r][3] = fmaf(a.y, w1.w, acc[r][3]);
            acc[r][0] = fmaf(a.z, w2.x, acc[r][0]);
            acc[r][1] = fmaf(a.z, w2.y, acc[r][1]);
            acc[r][2] = fmaf(a.z, w2.z, acc[r][2]);
            acc[r][3] = fmaf(a.z, w2.w, acc[r][3]);
            acc[r][0] = fmaf(a.w, w3.x, acc[r][0]);
            acc[r][1] = fmaf(a.w, w3.y, acc[r][1]);
            acc[r][2] = fmaf(a.w, w3.z, acc[r][2]);
            acc[r][3] = fmaf(a.w, w3.w, acc[r][3]);
        }
    }

    const float4 bv = __ldg((const float4*)&b[j0]);
    #pragma unroll
    for (int r = 0; r < 8; r++) {
        const int row = r0 + rb + r;
        if (row < NN) {
            float4 o;
            o.x = fmaxf(acc[r][0] + bv.x, 0.f);
            o.y = fmaxf(acc[r][1] + bv.y, 0.f);
            o.z = fmaxf(acc[r][2] + bv.z, 0.f);
            o.w = fmaxf(acc[r][3] + bv.w, 0.f);
            *(float4*)&C[(size_t)row * HID + j0] = o;
        }
    }
}

// ---------------- global mean pool ----------------
__global__ __launch_bounds__(256) void pool_sum(const long long* __restrict__ batch) {
    const long long idx = (long long)blockIdx.x * 256 + threadIdx.x;  // over N*HID/4
    if (idx < (long long)NN * HID / 4) {
        const int n = (int)(idx / (HID / 4));
        const int c = (int)(idx % (HID / 4)) * 4;
        const int g = load_idx(batch, n);
        const float4 v = *(const float4*)&g_x2[(size_t)n * HID + c];
        red_add_v4(&g_psum[g * HID + c], v.x, v.y, v.z, v.w);
        if (c == 0) atomicAdd(&g_pcnt[g], 1.0f);
    }
}

__global__ __launch_bounds__(256) void pool_final(float* __restrict__ out) {
    const int idx = blockIdx.x * 256 + threadIdx.x;  // G*HID = 16384
    const int g = idx >> 8;
    const float cnt = fmaxf(g_pcnt[g], 1.0f);
    out[idx] = g_psum[idx] / cnt;
}

// ---------------- launch ----------------
extern "C" void kernel_launch(void* const* d_in, const int* in_sizes, int n_in,
                              void* d_out, int out_size)
{
    const float*      x     = (const float*)d_in[0];
    const float*      ea    = (const float*)d_in[1];
    const long long*  eidx  = (const long long*)d_in[2];
    const long long*  batch = (const long long*)d_in[3];
    const float*      we1   = (const float*)d_in[4];
    const float*      be1   = (const float*)d_in[5];
    const float*      we2   = (const float*)d_in[6];
    const float*      be2   = (const float*)d_in[7];
    const float*      l0_lw = (const float*)d_in[8];
    const float*      l0_lb = (const float*)d_in[9];
    const float*      l0_w1 = (const float*)d_in[10];
    const float*      l0_b1 = (const float*)d_in[11];
    const float*      l0_w2 = (const float*)d_in[12];
    const float*      l0_b2 = (const float*)d_in[13];
    const float*      l1_lw = (const float*)d_in[14];
    const float*      l1_lb = (const float*)d_in[15];
    const float*      l1_w1 = (const float*)d_in[16];
    const float*      l1_b1 = (const float*)d_in[17];
    const float*      l1_w2 = (const float*)d_in[18];
    const float*      l1_b2 = (const float*)d_in[19];
    float* out = (float*)d_out;

    cudaFuncSetAttribute(edge_mma<0>, cudaFuncAttributeMaxDynamicSharedMemorySize,
                         EdgeSmem<0>::BYTES);
    cudaFuncSetAttribute(edge_mma<1>, cudaFuncAttributeMaxDynamicSharedMemorySize,
                         EdgeSmem<1>::BYTES);

    const int node_blocks = (NN + 31) / 32;

    // launch order matters for ncu: the 4th launch gets captured -> edge_mma<0>
    zero_kernel<<<NN * HID / 256, 256>>>(eidx);                     // 1
    prep_wc<0><<<HID / 8, 256>>>(we2, l0_lw, be2, l0_lb);           // 2
    prep_wc<1><<<HID / 8, 256>>>(we2, l1_lw, be2, l1_lb);           // 3

    // ---- layer 0 ----
    edge_mma<0><<<EE / 64, 256, EdgeSmem<0>::BYTES>>>(ea, eidx, we1, be1, x);   // 4
    node_mlp<0><<<node_blocks, 256>>>(x, l0_w1, l0_b1);
    node_mlp<1><<<node_blocks, 256>>>(nullptr, l0_w2, l0_b2);

    // ---- layer 1 ----
    edge_mma<1><<<EE / 64, 256, EdgeSmem<1>::BYTES>>>(ea, eidx, we1, be1, nullptr);
    node_mlp<2><<<node_blocks, 256>>>(nullptr, l1_w1, l1_b1);
    node_mlp<3><<<node_blocks, 256>>>(nullptr, l1_w2, l1_b2);

    // ---- global mean pool ----
    pool_sum<<<NN * HID / 4 / 256, 256>>>(batch);
    pool_final<<<GG * HID / 256, 256>>>(out);
}

// round 11
// speedup vs baseline: 1.0462x; 1.0462x over previous
#include <cuda_runtime.h>
#include <cstdint>

#define NN   10000
#define EE   320000
#define GG   64
#define NIN  64
#define EIN  16
#define HID  256

// ---------------- scratch (device-side only; NEVER passed from host) ----------------
__device__ __align__(16) float g_W0c[HID * NIN];    // tf32(we2 @ l0_lw)
__device__ __align__(16) float g_c0[NIN];           // be2 @ l0_lw + l0_lb
__device__ __align__(16) float g_W1c[HID * HID];    // tf32(we2 @ l1_lw)
__device__ __align__(16) float g_c1[HID];           // be2 @ l1_lw + l1_lb
__device__ __align__(16) float g_agg0[NN * NIN];
__device__ __align__(16) float g_agg1[NN * HID];
__device__ __align__(16) float g_t0[NN * HID];
__device__ __align__(16) float g_x1[NN * HID];
__device__ __align__(16) float g_x2[NN * HID];
__device__ __align__(16) float g_psum[GG * HID];
__device__ float g_pcnt[GG];
__device__ int   g_is64;

// ---------------- helpers ----------------
__device__ __forceinline__ int load_idx(const void* p, long long i) {
    if (g_is64) return (int)((const long long*)p)[i];
    return ((const int*)p)[i];
}

__device__ __forceinline__ void red_add_v4(float* p, float a, float b, float c, float d) {
    asm volatile("red.global.add.v4.f32 [%0], {%1, %2, %3, %4};"
                 :: "l"(p), "f"(a), "f"(b), "f"(c), "f"(d) : "memory");
}

__device__ __forceinline__ float to_tf32(float x) {
    unsigned r;
    asm("cvt.rna.tf32.f32 %0, %1;" : "=r"(r) : "f"(x));
    return __uint_as_float(r);
}

// m16n8k8 tf32 MMA, D += A*B
__device__ __forceinline__ void mma_tf32(float* d,
    uint32_t a0, uint32_t a1, uint32_t a2, uint32_t a3,
    uint32_t b0, uint32_t b1)
{
    asm volatile(
        "mma.sync.aligned.m16n8k8.row.col.f32.tf32.tf32.f32 "
        "{%0,%1,%2,%3}, {%4,%5,%6,%7}, {%8,%9}, {%0,%1,%2,%3};"
        : "+f"(d[0]), "+f"(d[1]), "+f"(d[2]), "+f"(d[3])
        : "r"(a0), "r"(a1), "r"(a2), "r"(a3), "r"(b0), "r"(b1));
}

// zero scratch + detect index width (merged so edge_mma<0> is the 4th launch)
__global__ void zero_kernel(const long long* eidx) {
    int i = blockIdx.x * 256 + threadIdx.x;   // grid covers NN*HID = 2.56M exactly
    if (i < NN * NIN) g_agg0[i] = 0.f;
    if (i < NN * HID) g_agg1[i] = 0.f;
    if (i < GG * HID) g_psum[i] = 0.f;
    if (i < GG)       g_pcnt[i] = 0.f;
    if (i == 0) {
        int is64 = 1;
        #pragma unroll 1
        for (int k = 0; k < 64; k++) {
            long long v = eidx[k];
            if (v < 0 || v >= NN) { is64 = 0; break; }
        }
        g_is64 = is64;
    }
}

// ---------------- weight folding: Wc = tf32(we2 @ lw) ; c = be2 @ lw + lb ----------------
template<int LAYER>
__global__ __launch_bounds__(256) void prep_wc(const float* __restrict__ we2,
                                               const float* __restrict__ lw,
                                               const float* __restrict__ be2,
                                               const float* __restrict__ lb) {
    constexpr int COUT = (LAYER == 0) ? NIN : HID;
    float* wc = (LAYER == 0) ? g_W0c : g_W1c;
    float* cv = (LAYER == 0) ? g_c0  : g_c1;
    __shared__ float lw_s[32][256];
    __shared__ float we2_s[8][33];
    const int i0 = blockIdx.x * 8;
    const int t = threadIdx.x;
    float acc[8];
    #pragma unroll
    for (int r = 0; r < 8; r++) acc[r] = 0.f;

    #pragma unroll 1
    for (int kc = 0; kc < HID; kc += 32) {
        __syncthreads();
        for (int i = t; i < 32 * COUT / 4; i += 256) {
            const int r = i / (COUT / 4), c = (i % (COUT / 4)) * 4;
            *(float4*)&lw_s[r][c] = __ldg((const float4*)&lw[(kc + r) * COUT + c]);
        }
        we2_s[t >> 5][t & 31] = we2[(i0 + (t >> 5)) * HID + kc + (t & 31)];
        __syncthreads();
        if (t < COUT) {
            #pragma unroll 4
            for (int k = 0; k < 32; k++) {
                const float wv = lw_s[k][t];
                #pragma unroll
                for (int r = 0; r < 8; r++) acc[r] = fmaf(we2_s[r][k], wv, acc[r]);
            }
        }
    }
    if (t < COUT) {
        #pragma unroll
        for (int r = 0; r < 8; r++) wc[(i0 + r) * COUT + t] = to_tf32(acc[r]);
        if (blockIdx.x == 0) {
            float a = lb[t];
            #pragma unroll 4
            for (int k = 0; k < HID; k++) a = fmaf(be2[k], lw[k * COUT + t], a);
            cv[t] = a;
        }
    }
}

// ---------------- fused edge kernel, TF32 mma.sync, fragment-reuse tiling ----------------
// 64 edges / block, 8 warps. Each warp owns ALL 64 M rows x a private N slice
// (32 cols phase1, COUT/8 cols phase2): B fragments loaded once per 8-k step and
// reused across 4 M tiles -> 1.5 LDS per MMA (was 2.25-3.0).
template<int LAYER>
__global__ __launch_bounds__(256, 2) void edge_mma(
    const float* __restrict__ ea,
    const long long* __restrict__ eidx,
    const float* __restrict__ we1,
    const float* __restrict__ be1,
    const float* __restrict__ x_arg)
{
    constexpr int COUT  = (LAYER == 0) ? NIN : HID;
    constexpr int NPAD1 = HID + 8;     // 264
    constexpr int NPAD2 = COUT + 8;
    constexpr int H1S   = HID + 4;     // 260
    constexpr int EAS   = 20;
    constexpr int BSZ   = (16 * NPAD1 > 32 * NPAD2) ? 16 * NPAD1 : 32 * NPAD2;
    constexpr int NT2   = COUT / 64;   // phase-2 n-tiles per warp (4 or 1)

    const float* Wc   = (LAYER == 0) ? g_W0c : g_W1c;   // pre-rounded tf32
    const float* cvec = (LAYER == 0) ? g_c0  : g_c1;
    const float* xin  = (LAYER == 0) ? x_arg : g_x1;
    float*       agg  = (LAYER == 0) ? g_agg0 : g_agg1;

    extern __shared__ float sm[];
    float* ea_s  = sm;                    // 64*EAS
    float* h1_s  = ea_s + 64 * EAS;       // 64*H1S
    float* Bs    = h1_s + 64 * H1S;       // BSZ
    float* be1_s = Bs + BSZ;              // HID
    float* c_s   = be1_s + HID;           // COUT
    int*   src_s = (int*)(c_s + COUT);    // 64 ints
    int*   dst_s = src_s + 64;            // 64 ints

    const int t  = threadIdx.x;
    const long long e0 = (long long)blockIdx.x * 64;

    // ---- loads ----
    {   // ea: 64x16, one float4 per thread, tf32-rounded
        const int e = t >> 2, c = (t & 3) * 4;
        float4 v = *(const float4*)&ea[(e0 + e) * EIN + c];
        v.x = to_tf32(v.x); v.y = to_tf32(v.y); v.z = to_tf32(v.z); v.w = to_tf32(v.w);
        *(float4*)&ea_s[e * EAS + c] = v;
    }
    if (t < 64)       src_s[t]      = load_idx(eidx, e0 + t);
    else if (t < 128) dst_s[t - 64] = load_idx(eidx, (long long)EE + e0 + (t - 64));
    be1_s[t] = be1[t];
    if (t < COUT) c_s[t] = cvec[t];
    {   // we1 (16x256) into Bs, tf32-rounded
        const int r = t >> 4, cb = (t & 15) * 16;
        #pragma unroll
        for (int i = 0; i < 4; i++) {
            float4 v = __ldg((const float4*)&we1[r * HID + cb + i * 4]);
            v.x = to_tf32(v.x); v.y = to_tf32(v.y); v.z = to_tf32(v.z); v.w = to_tf32(v.w);
            *(float4*)&Bs[r * NPAD1 + cb + i * 4] = v;
        }
    }
    __syncthreads();

    const int w  = t >> 5, l = t & 31;
    const int lq = l >> 2, lr = l & 3;

    float d[4][4][4];   // [m-tile][n-tile][c-reg]

    // ---- phase 1: h1 = relu(ea @ we1 + be1); warp n-slice = w*32..w*32+31 ----
    {
        const int n1 = w * 32;
        #pragma unroll
        for (int m = 0; m < 4; m++)
            #pragma unroll
            for (int nt = 0; nt < 4; nt++)
                { d[m][nt][0] = d[m][nt][1] = d[m][nt][2] = d[m][nt][3] = 0.f; }

        #pragma unroll
        for (int ks = 0; ks < 2; ks++) {
            const int k = ks * 8;
            uint32_t bf[4][2];
            #pragma unroll
            for (int nt = 0; nt < 4; nt++) {
                const int n = n1 + nt * 8 + lq;
                bf[nt][0] = __float_as_uint(Bs[(k + lr) * NPAD1 + n]);
                bf[nt][1] = __float_as_uint(Bs[(k + lr + 4) * NPAD1 + n]);
            }
            #pragma unroll
            for (int m = 0; m < 4; m++) {
                const int row = m * 16 + lq;
                const uint32_t a0 = __float_as_uint(ea_s[row * EAS + k + lr]);
                const uint32_t a1 = __float_as_uint(ea_s[(row + 8) * EAS + k + lr]);
                const uint32_t a2 = __float_as_uint(ea_s[row * EAS + k + lr + 4]);
                const uint32_t a3 = __float_as_uint(ea_s[(row + 8) * EAS + k + lr + 4]);
                #pragma unroll
                for (int nt = 0; nt < 4; nt++)
                    mma_tf32(d[m][nt], a0, a1, a2, a3, bf[nt][0], bf[nt][1]);
            }
        }
        #pragma unroll
        for (int m = 0; m < 4; m++) {
            const int row = m * 16 + lq;
            #pragma unroll
            for (int nt = 0; nt < 4; nt++) {
                const int n = n1 + nt * 8 + lr * 2;
                const float bv0 = be1_s[n], bv1 = be1_s[n + 1];
                h1_s[row * H1S + n]           = to_tf32(fmaxf(d[m][nt][0] + bv0, 0.f));
                h1_s[row * H1S + n + 1]       = to_tf32(fmaxf(d[m][nt][1] + bv1, 0.f));
                h1_s[(row + 8) * H1S + n]     = to_tf32(fmaxf(d[m][nt][2] + bv0, 0.f));
                h1_s[(row + 8) * H1S + n + 1] = to_tf32(fmaxf(d[m][nt][3] + bv1, 0.f));
            }
        }
    }

    // ---- phase 2: ep = h1 @ Wc; warp n-slice = w*(COUT/8), NT2 n-tiles ----
    const int n2 = w * (COUT / 8);
    #pragma unroll
    for (int m = 0; m < 4; m++)
        #pragma unroll
        for (int nt = 0; nt < NT2; nt++)
            { d[m][nt][0] = d[m][nt][1] = d[m][nt][2] = d[m][nt][3] = 0.f; }

    #pragma unroll 1
    for (int kc = 0; kc < HID; kc += 32) {
        __syncthreads();   // prior Bs readers done
        for (int i = t; i < 32 * COUT / 4; i += 256) {
            const int r = i / (COUT / 4), c = (i % (COUT / 4)) * 4;
            *(float4*)&Bs[r * NPAD2 + c] = __ldg((const float4*)&Wc[(size_t)(kc + r) * COUT + c]);
        }
        __syncthreads();
        #pragma unroll
        for (int ks = 0; ks < 4; ks++) {
            const int k = ks * 8;
            uint32_t bf[NT2][2];
            #pragma unroll
            for (int nt = 0; nt < NT2; nt++) {
                const int n = n2 + nt * 8 + lq;
                bf[nt][0] = __float_as_uint(Bs[(k + lr) * NPAD2 + n]);
                bf[nt][1] = __float_as_uint(Bs[(k + lr + 4) * NPAD2 + n]);
            }
            #pragma unroll
            for (int m = 0; m < 4; m++) {
                const int row = m * 16 + lq;
                const uint32_t a0 = __float_as_uint(h1_s[row * H1S + kc + k + lr]);
                const uint32_t a1 = __float_as_uint(h1_s[(row + 8) * H1S + kc + k + lr]);
                const uint32_t a2 = __float_as_uint(h1_s[row * H1S + kc + k + lr + 4]);
                const uint32_t a3 = __float_as_uint(h1_s[(row + 8) * H1S + kc + k + lr + 4]);
                #pragma unroll
                for (int nt = 0; nt < NT2; nt++)
                    mma_tf32(d[m][nt], a0, a1, a2, a3, bf[nt][0], bf[nt][1]);
            }
        }
    }

    __syncthreads();   // all h1 reads done; safe to overwrite with ep
    #pragma unroll
    for (int m = 0; m < 4; m++) {
        const int row = m * 16 + lq;
        #pragma unroll
        for (int nt = 0; nt < NT2; nt++) {
            const int n = n2 + nt * 8 + lr * 2;
            h1_s[row * H1S + n]           = d[m][nt][0];
            h1_s[row * H1S + n + 1]       = d[m][nt][1];
            h1_s[(row + 8) * H1S + n]     = d[m][nt][2];
            h1_s[(row + 8) * H1S + n + 1] = d[m][nt][3];
        }
    }
    __syncthreads();

    // ---- scatter: msg = relu(x[src] + ep + c) -> RED.128 into agg[dst] ----
    constexpr int CG = COUT / 4;
    for (int i = t; i < 64 * CG; i += 256) {
        const int e = i / CG, c = (i % CG) * 4;
        const float4 ep = *(const float4*)&h1_s[e * H1S + c];
        const float4 xv = __ldg((const float4*)&xin[(size_t)src_s[e] * COUT + c]);
        const float4 cv = *(const float4*)&c_s[c];
        red_add_v4(&agg[(size_t)dst_s[e] * COUT + c],
                   fmaxf(xv.x + ep.x + cv.x, 0.f),
                   fmaxf(xv.y + ep.y + cv.y, 0.f),
                   fmaxf(xv.z + ep.z + cv.z, 0.f),
                   fmaxf(xv.w + ep.w + cv.w, 0.f));
    }
}

template<int LAYER> struct EdgeSmem {
    static constexpr int COUT  = (LAYER == 0) ? NIN : HID;
    static constexpr int NPAD1 = HID + 8;
    static constexpr int NPAD2 = COUT + 8;
    static constexpr int BSZ   = (16 * NPAD1 > 32 * NPAD2) ? 16 * NPAD1 : 32 * NPAD2;
    static constexpr int FLOATS = 64 * 20 + 64 * (HID + 4) + BSZ + HID + COUT + 128;
    static constexpr int BYTES  = FLOATS * 4;
};

// ---------------- node MLP (fp32 FMA): C = relu((A [+ A2]) @ W + b) ----------------
// MODE 0: A=x (K=64) +g_agg0 -> g_t0 ; MODE 1: A=g_t0 -> g_x1
// MODE 2: A=g_x1 +g_agg1 -> g_t0     ; MODE 3: A=g_t0 -> g_x2
template<int MODE>
__global__ __launch_bounds__(256) void node_mlp(
    const float* __restrict__ x_arg,
    const float* __restrict__ W,
    const float* __restrict__ b)
{
    constexpr int  K   = (MODE == 0) ? NIN : HID;
    constexpr bool ADD = (MODE == 0) || (MODE == 2);
    const float* A  = (MODE == 0) ? x_arg :
                      (MODE == 2) ? g_x1  : g_t0;
    const float* A2 = (MODE == 0) ? g_agg0 : g_agg1;
    float*       C  = (MODE == 1) ? g_x1 :
                      (MODE == 3) ? g_x2 : g_t0;

    __shared__ float a_s[32][K + 4];
    const int t = threadIdx.x;
    const int r0 = blockIdx.x * 32;

    #pragma unroll 1
    for (int i = t; i < 32 * K; i += 256) {
        const int r = i / K, k = i % K;
        float v = 0.f;
        if (r0 + r < NN) {
            v = A[(size_t)(r0 + r) * K + k];
            if (ADD) v += A2[(size_t)(r0 + r) * K + k];
        }
        a_s[r][k] = v;
    }
    __syncthreads();

    const int j0 = (t % 64) * 4;
    const int rb = (t / 64) * 8;
    float acc[8][4];
    #pragma unroll
    for (int r = 0; r < 8; r++) { acc[r][0] = acc[r][1] = acc[r][2] = acc[r][3] = 0.f; }

    #pragma unroll 1
    for (int k = 0; k < K; k += 4) {
        const float4 w0 = __ldg((const float4*)&W[(k + 0) * HID + j0]);
        const float4 w1 = __ldg((const float4*)&W[(k + 1) * HID + j0]);
        const float4 w2 = __ldg((const float4*)&W[(k + 2) * HID + j0]);
        const float4 w3 = __ldg((const float4*)&W[(k + 3) * HID + j0]);
        #pragma unroll
        for (int r = 0; r < 8; r++) {
            const float4 a = *(const float4*)&a_s[rb + r][k];
            acc[r][0] = fmaf(a.x, w0.x, acc[r][0]);
            acc[r][1] = fmaf(a.x, w0.y, acc[r][1]);
            acc[r][2] = fmaf(a.x, w0.z, acc[r][2]);
            acc[r][3] = fmaf(a.x, w0.w, acc[r][3]);
            acc[r][0] = fmaf(a.y, w1.x, acc[r][0]);
            acc[r][1] = fmaf(a.y, w1.y, acc[r][1]);
            acc[r][2] = fmaf(a.y, w1.z, acc[r][2]);
            acc[r][3] = fmaf(a.y, w1.w, acc[r][3]);
            acc[r][0] = fmaf(a.z, w2.x, acc[r][0]);
            acc[r][1] = fmaf(a.z, w2.y, acc[r][1]);
            acc[r][2] = fmaf(a.z, w2.z, acc[r][2]);
            acc[r][3] = fmaf(a.z, w2.w, acc[r][3]);
            acc[r][0] = fmaf(a.w, w3.x, acc[r][0]);
            acc[r][1] = fmaf(a.w, w3.y, acc[r][1]);
            acc[r][2] = fmaf(a.w, w3.z, acc[r][2]);
            acc[r][3] = fmaf(a.w, w3.w, acc[r][3]);
        }
    }

    const float4 bv = __ldg((const float4*)&b[j0]);
    #pragma unroll
    for (int r = 0; r < 8; r++) {
        const int row = r0 + rb + r;
        if (row < NN) {
            float4 o;
            o.x = fmaxf(acc[r][0] + bv.x, 0.f);
            o.y = fmaxf(acc[r][1] + bv.y, 0.f);
            o.z = fmaxf(acc[r][2] + bv.z, 0.f);
            o.w = fmaxf(acc[r][3] + bv.w, 0.f);
            *(float4*)&C[(size_t)row * HID + j0] = o;
        }
    }
}

// ---------------- global mean pool ----------------
__global__ __launch_bounds__(256) void pool_sum(const long long* __restrict__ batch) {
    const long long idx = (long long)blockIdx.x * 256 + threadIdx.x;  // over N*HID/4
    if (idx < (long long)NN * HID / 4) {
        const int n = (int)(idx / (HID / 4));
        const int c = (int)(idx % (HID / 4)) * 4;
        const int g = load_idx(batch, n);
        const float4 v = *(const float4*)&g_x2[(size_t)n * HID + c];
        red_add_v4(&g_psum[g * HID + c], v.x, v.y, v.z, v.w);
        if (c == 0) atomicAdd(&g_pcnt[g], 1.0f);
    }
}

__global__ __launch_bounds__(256) void pool_final(float* __restrict__ out) {
    const int idx = blockIdx.x * 256 + threadIdx.x;  // G*HID = 16384
    const int g = idx >> 8;
    const float cnt = fmaxf(g_pcnt[g], 1.0f);
    out[idx] = g_psum[idx] / cnt;
}

// ---------------- launch ----------------
extern "C" void kernel_launch(void* const* d_in, const int* in_sizes, int n_in,
                              void* d_out, int out_size)
{
    const float*      x     = (const float*)d_in[0];
    const float*      ea    = (const float*)d_in[1];
    const long long*  eidx  = (const long long*)d_in[2];
    const long long*  batch = (const long long*)d_in[3];
    const float*      we1   = (const float*)d_in[4];
    const float*      be1   = (const float*)d_in[5];
    const float*      we2   = (const float*)d_in[6];
    const float*      be2   = (const float*)d_in[7];
    const float*      l0_lw = (const float*)d_in[8];
    const float*      l0_lb = (const float*)d_in[9];
    const float*      l0_w1 = (const float*)d_in[10];
    const float*      l0_b1 = (const float*)d_in[11];
    const float*      l0_w2 = (const float*)d_in[12];
    const float*      l0_b2 = (const float*)d_in[13];
    const float*      l1_lw = (const float*)d_in[14];
    const float*      l1_lb = (const float*)d_in[15];
    const float*      l1_w1 = (const float*)d_in[16];
    const float*      l1_b1 = (const float*)d_in[17];
    const float*      l1_w2 = (const float*)d_in[18];
    const float*      l1_b2 = (const float*)d_in[19];
    float* out = (float*)d_out;

    cudaFuncSetAttribute(edge_mma<0>, cudaFuncAttributeMaxDynamicSharedMemorySize,
                         EdgeSmem<0>::BYTES);
    cudaFuncSetAttribute(edge_mma<1>, cudaFuncAttributeMaxDynamicSharedMemorySize,
                         EdgeSmem<1>::BYTES);

    const int node_blocks = (NN + 31) / 32;

    // launch order matters for ncu: the 4th launch gets captured -> edge_mma<0>
    zero_kernel<<<NN * HID / 256, 256>>>(eidx);                     // 1
    prep_wc<0><<<HID / 8, 256>>>(we2, l0_lw, be2, l0_lb);           // 2
    prep_wc<1><<<HID / 8, 256>>>(we2, l1_lw, be2, l1_lb);           // 3

    // ---- layer 0 ----
    edge_mma<0><<<EE / 64, 256, EdgeSmem<0>::BYTES>>>(ea, eidx, we1, be1, x);   // 4
    node_mlp<0><<<node_blocks, 256>>>(x, l0_w1, l0_b1);
    node_mlp<1><<<node_blocks, 256>>>(nullptr, l0_w2, l0_b2);

    // ---- layer 1 ----
    edge_mma<1><<<EE / 64, 256, EdgeSmem<1>::BYTES>>>(ea, eidx, we1, be1, nullptr);
    node_mlp<2><<<node_blocks, 256>>>(nullptr, l1_w1, l1_b1);
    node_mlp<3><<<node_blocks, 256>>>(nullptr, l1_w2, l1_b2);

    // ---- global mean pool ----
    pool_sum<<<NN * HID / 4 / 256, 256>>>(batch);
    pool_final<<<GG * HID / 256, 256>>>(out);
}